// round 15
// baseline (speedup 1.0000x reference)
#include <cuda_runtime.h>
#include <cuda_bf16.h>
#include <mma.h>
#include <math.h>
#include <cstdint>

using namespace nvcuda;

#define Bb 128
#define Ss 256
#define Ii 512
#define Oo 512
#define Hh 1024
#define G3 3072
#define RWS (Ss*Bb)

// ---------------- scratch ----------------
__device__ __align__(16) float g_yT[16777216];    // [s*B+b][I]
__device__ int   g_idx[RWS];
__device__ __align__(16) float g_gi[100663296];   // [s*B+b][3H] raw gemm
__device__ __align__(16) float g_gh4[4*Bb*G3];    // 4 K-split partials
__device__ __align__(16) float g_hs[33685504];    // [(s+1)][B][H]
__device__ __align__(16) float g_hsB[33554432];   // [b*S+s][H]
__device__ __align__(16) float g_lg[16777216];    // raw logits
__device__ __align__(16) float g_WtgtT[Oo*G3];
__device__ __align__(16) __nv_bfloat16 g_hH16[Bb*Hh], g_hL16[Bb*Hh];   // packed h
__device__ __align__(16) __nv_bfloat16 g_WhhHi[G3*1024], g_WhhLo[G3*1024];
__device__ __align__(16) __nv_bfloat16 g_WihHi[G3*1024], g_WihLo[G3*1024];
__device__ __align__(16) __nv_bfloat16 g_LwHi[Oo*1024],  g_LwLo[Oo*1024];

typedef wmma::fragment<wmma::matrix_a, 16,16,16, __nv_bfloat16, wmma::row_major> FragA;
typedef wmma::fragment<wmma::matrix_b, 16,16,16, __nv_bfloat16, wmma::col_major> FragB;
typedef wmma::fragment<wmma::accumulator, 16,16,16, float> FragC;

#define SROW 20
#define SROW_E 40
#define STG96  8960    // k_ghB stage: AHi 0, ALo 2560, BHi 5120, BLo 7040

__device__ __forceinline__ void cvt16(const float4 v0, const float4 v1, uint4& hi, uint4& lo){
    __nv_bfloat16 h0, h1, l0, l1;
    h0=__float2bfloat16(v0.x); h1=__float2bfloat16(v0.y);
    l0=__float2bfloat16(v0.x-__bfloat162float(h0)); l1=__float2bfloat16(v0.y-__bfloat162float(h1));
    hi.x = ((uint32_t)__bfloat16_as_ushort(h1)<<16) | __bfloat16_as_ushort(h0);
    lo.x = ((uint32_t)__bfloat16_as_ushort(l1)<<16) | __bfloat16_as_ushort(l0);
    h0=__float2bfloat16(v0.z); h1=__float2bfloat16(v0.w);
    l0=__float2bfloat16(v0.z-__bfloat162float(h0)); l1=__float2bfloat16(v0.w-__bfloat162float(h1));
    hi.y = ((uint32_t)__bfloat16_as_ushort(h1)<<16) | __bfloat16_as_ushort(h0);
    lo.y = ((uint32_t)__bfloat16_as_ushort(l1)<<16) | __bfloat16_as_ushort(l0);
    h0=__float2bfloat16(v1.x); h1=__float2bfloat16(v1.y);
    l0=__float2bfloat16(v1.x-__bfloat162float(h0)); l1=__float2bfloat16(v1.y-__bfloat162float(h1));
    hi.z = ((uint32_t)__bfloat16_as_ushort(h1)<<16) | __bfloat16_as_ushort(h0);
    lo.z = ((uint32_t)__bfloat16_as_ushort(l1)<<16) | __bfloat16_as_ushort(l0);
    h0=__float2bfloat16(v1.z); h1=__float2bfloat16(v1.w);
    l0=__float2bfloat16(v1.z-__bfloat162float(h0)); l1=__float2bfloat16(v1.w-__bfloat162float(h1));
    hi.w = ((uint32_t)__bfloat16_as_ushort(h1)<<16) | __bfloat16_as_ushort(h0);
    lo.w = ((uint32_t)__bfloat16_as_ushort(l1)<<16) | __bfloat16_as_ushort(l0);
}

// ---------------- wmma compute stages ----------------
__device__ __forceinline__ void mma_stage(
    const uint32_t* sAHi, const uint32_t* sALo,
    const uint32_t* sBHi, const uint32_t* sBLo,
    int rowOff, int colOff, FragC acc[2][4])
{
    const __nv_bfloat16* eAh = reinterpret_cast<const __nv_bfloat16*>(sAHi);
    const __nv_bfloat16* eAl = reinterpret_cast<const __nv_bfloat16*>(sALo);
    const __nv_bfloat16* eBh = reinterpret_cast<const __nv_bfloat16*>(sBHi);
    const __nv_bfloat16* eBl = reinterpret_cast<const __nv_bfloat16*>(sBLo);
    #pragma unroll
    for (int ks = 0; ks < 2; ++ks){
        FragA ah[2], al[2];
        #pragma unroll
        for (int mi = 0; mi < 2; ++mi){
            wmma::load_matrix_sync(ah[mi], eAh + (rowOff + mi*16)*SROW_E + ks*16, SROW_E);
            wmma::load_matrix_sync(al[mi], eAl + (rowOff + mi*16)*SROW_E + ks*16, SROW_E);
        }
        #pragma unroll
        for (int ni = 0; ni < 4; ++ni){
            FragB bh, bl;
            wmma::load_matrix_sync(bh, eBh + (colOff + ni*16)*SROW_E + ks*16, SROW_E);
            wmma::load_matrix_sync(bl, eBl + (colOff + ni*16)*SROW_E + ks*16, SROW_E);
            #pragma unroll
            for (int mi = 0; mi < 2; ++mi){
                wmma::mma_sync(acc[mi][ni], ah[mi], bh, acc[mi][ni]);
                wmma::mma_sync(acc[mi][ni], ah[mi], bl, acc[mi][ni]);
                wmma::mma_sync(acc[mi][ni], al[mi], bh, acc[mi][ni]);
            }
        }
    }
}

__device__ __forceinline__ void mma_stage96(
    const uint32_t* sAHi, const uint32_t* sALo,
    const uint32_t* sBHi, const uint32_t* sBLo,
    int rowOff, int colOff, FragC acc[2][3])
{
    const __nv_bfloat16* eAh = reinterpret_cast<const __nv_bfloat16*>(sAHi);
    const __nv_bfloat16* eAl = reinterpret_cast<const __nv_bfloat16*>(sALo);
    const __nv_bfloat16* eBh = reinterpret_cast<const __nv_bfloat16*>(sBHi);
    const __nv_bfloat16* eBl = reinterpret_cast<const __nv_bfloat16*>(sBLo);
    #pragma unroll
    for (int ks = 0; ks < 2; ++ks){
        FragA ah[2], al[2];
        #pragma unroll
        for (int mi = 0; mi < 2; ++mi){
            wmma::load_matrix_sync(ah[mi], eAh + (rowOff + mi*16)*SROW_E + ks*16, SROW_E);
            wmma::load_matrix_sync(al[mi], eAl + (rowOff + mi*16)*SROW_E + ks*16, SROW_E);
        }
        #pragma unroll
        for (int ni = 0; ni < 3; ++ni){
            FragB bh, bl;
            wmma::load_matrix_sync(bh, eBh + (colOff + ni*16)*SROW_E + ks*16, SROW_E);
            wmma::load_matrix_sync(bl, eBl + (colOff + ni*16)*SROW_E + ks*16, SROW_E);
            #pragma unroll
            for (int mi = 0; mi < 2; ++mi){
                wmma::mma_sync(acc[mi][ni], ah[mi], bh, acc[mi][ni]);
                wmma::mma_sync(acc[mi][ni], ah[mi], bl, acc[mi][ni]);
                wmma::mma_sync(acc[mi][ni], al[mi], bh, acc[mi][ni]);
            }
        }
    }
}

// copy a 128x32 bf16 tile from global into padded smem
__device__ __forceinline__ void copy_tile16(uint32_t* dst, const __nv_bfloat16* __restrict__ src,
                                            int ld, int rowBase, int k0){
    int t = threadIdx.x;
    #pragma unroll
    for (int it = 0; it < 2; ++it){
        int idx = it*256 + t;
        int row = idx >> 2, seg = idx & 3;
        *reinterpret_cast<uint4*>(dst + row*SROW + seg*4) =
            *reinterpret_cast<const uint4*>(src + (size_t)(rowBase+row)*ld + k0 + seg*8);
    }
}

// ---------------- wmma GEMM, static smem (R13-proven; 2 CTA/SM) ----------------
__device__ __forceinline__ void wmma_gemm(
    const float* __restrict__ Asrc, int lda, int mBase,
    const __nv_bfloat16* __restrict__ BHi, const __nv_bfloat16* __restrict__ BLo,
    int ldb, int nBase, int k0, int nChunks,
    float* __restrict__ dst, int ldd)
{
    __shared__ __align__(16) uint32_t sAHi[128*SROW], sALo[128*SROW];
    __shared__ __align__(16) uint32_t sBHi[128*SROW], sBLo[128*SROW];
    int t = threadIdx.x;
    FragC acc[2][4];
    #pragma unroll
    for (int mi = 0; mi < 2; ++mi)
        #pragma unroll
        for (int ni = 0; ni < 4; ++ni) wmma::fill_fragment(acc[mi][ni], 0.f);
    int w = t >> 5;
    int rowOff = (w&3)*32, colOff = (w>>2)*64;
    for (int c = 0; c < nChunks; ++c){
        int kc = k0 + c*32;
        #pragma unroll
        for (int it = 0; it < 2; ++it){
            int idx = it*256 + t;
            int row = idx >> 2, seg = idx & 3;
            const float* p = Asrc + (size_t)(mBase + row)*lda + kc + seg*8;
            float4 v0 = *reinterpret_cast<const float4*>(p);
            float4 v1 = *reinterpret_cast<const float4*>(p + 4);
            uint4 hi, lo; cvt16(v0, v1, hi, lo);
            *reinterpret_cast<uint4*>(sAHi + row*SROW + seg*4) = hi;
            *reinterpret_cast<uint4*>(sALo + row*SROW + seg*4) = lo;
        }
        copy_tile16(sBHi, BHi, ldb, nBase, kc);
        copy_tile16(sBLo, BLo, ldb, nBase, kc);
        __syncthreads();
        mma_stage(sAHi, sALo, sBHi, sBLo, rowOff, colOff, acc);
        __syncthreads();
    }
    #pragma unroll
    for (int mi = 0; mi < 2; ++mi)
        #pragma unroll
        for (int ni = 0; ni < 4; ++ni)
            wmma::store_matrix_sync(dst + (size_t)(mBase + rowOff + mi*16)*ldd
                                        + nBase + colOff + ni*16,
                                    acc[mi][ni], ldd, wmma::mem_row_major);
}

// ---------------- recurrence GEMM: N-tile 96, 128 CTAs, 2-stage pipeline (R13 verbatim) ----------------
__global__ void __launch_bounds__(256, 1) k_ghB(){
    extern __shared__ __align__(16) uint32_t smb[];
    int nt = blockIdx.x, kz = blockIdx.y;
    int nBase = nt*96, k0 = kz*256;
    int t = threadIdx.x, w = t >> 5;
    int rowOff = (w&3)*32, colOff = (w>>2)*48;
    int ra0 = t >> 2,          sa0 = t & 3;
    int ra1 = (256+t) >> 2,    sa1 = t & 3;
    size_t a0 = (size_t)ra0*1024 + sa0*8,  a1 = (size_t)ra1*1024 + sa1*8;
    int da0 = ra0*SROW + sa0*4, da1 = ra1*SROW + sa1*4;
    int rb0 = t >> 2,          sb0 = t & 3;
    int rb1 = 64 + (t >> 2),   sb1 = t & 3;
    bool hasB1 = (t < 128);
    size_t b0 = (size_t)(nBase+rb0)*1024 + sb0*8;
    size_t b1 = (size_t)(nBase+rb1)*1024 + sb1*8;
    int db0 = rb0*SROW + sb0*4, db1 = rb1*SROW + sb1*4;

    FragC acc[2][3];
    #pragma unroll
    for (int mi = 0; mi < 2; ++mi)
        #pragma unroll
        for (int ni = 0; ni < 3; ++ni) wmma::fill_fragment(acc[mi][ni], 0.f);

    {
        int kc = k0;
        uint32_t* st = smb;
        *reinterpret_cast<uint4*>(st + da0)        = *reinterpret_cast<const uint4*>(g_hH16 + a0 + kc);
        *reinterpret_cast<uint4*>(st + da1)        = *reinterpret_cast<const uint4*>(g_hH16 + a1 + kc);
        *reinterpret_cast<uint4*>(st + 2560 + da0) = *reinterpret_cast<const uint4*>(g_hL16 + a0 + kc);
        *reinterpret_cast<uint4*>(st + 2560 + da1) = *reinterpret_cast<const uint4*>(g_hL16 + a1 + kc);
        *reinterpret_cast<uint4*>(st + 5120 + db0) = *reinterpret_cast<const uint4*>(g_WhhHi + b0 + kc);
        *reinterpret_cast<uint4*>(st + 7040 + db0) = *reinterpret_cast<const uint4*>(g_WhhLo + b0 + kc);
        if (hasB1){
            *reinterpret_cast<uint4*>(st + 5120 + db1) = *reinterpret_cast<const uint4*>(g_WhhHi + b1 + kc);
            *reinterpret_cast<uint4*>(st + 7040 + db1) = *reinterpret_cast<const uint4*>(g_WhhLo + b1 + kc);
        }
    }
    __syncthreads();

    #pragma unroll
    for (int c = 0; c < 8; ++c){
        uint4 rAh0, rAh1, rAl0, rAl1, rBh0, rBh1, rBl0, rBl1;
        if (c < 7){
            int kc = k0 + (c+1)*32;
            rAh0 = *reinterpret_cast<const uint4*>(g_hH16 + a0 + kc);
            rAh1 = *reinterpret_cast<const uint4*>(g_hH16 + a1 + kc);
            rAl0 = *reinterpret_cast<const uint4*>(g_hL16 + a0 + kc);
            rAl1 = *reinterpret_cast<const uint4*>(g_hL16 + a1 + kc);
            rBh0 = *reinterpret_cast<const uint4*>(g_WhhHi + b0 + kc);
            rBl0 = *reinterpret_cast<const uint4*>(g_WhhLo + b0 + kc);
            if (hasB1){
                rBh1 = *reinterpret_cast<const uint4*>(g_WhhHi + b1 + kc);
                rBl1 = *reinterpret_cast<const uint4*>(g_WhhLo + b1 + kc);
            }
        }
        const uint32_t* st = smb + (c & 1)*STG96;
        mma_stage96(st, st + 2560, st + 5120, st + 7040, rowOff, colOff, acc);
        if (c < 7){
            uint32_t* dt = smb + ((c+1) & 1)*STG96;
            *reinterpret_cast<uint4*>(dt + da0)        = rAh0;
            *reinterpret_cast<uint4*>(dt + da1)        = rAh1;
            *reinterpret_cast<uint4*>(dt + 2560 + da0) = rAl0;
            *reinterpret_cast<uint4*>(dt + 2560 + da1) = rAl1;
            *reinterpret_cast<uint4*>(dt + 5120 + db0) = rBh0;
            *reinterpret_cast<uint4*>(dt + 7040 + db0) = rBl0;
            if (hasB1){
                *reinterpret_cast<uint4*>(dt + 5120 + db1) = rBh1;
                *reinterpret_cast<uint4*>(dt + 7040 + db1) = rBl1;
            }
        }
        __syncthreads();
    }
    float* dst = g_gh4 + (size_t)kz*Bb*G3;
    #pragma unroll
    for (int mi = 0; mi < 2; ++mi)
        #pragma unroll
        for (int ni = 0; ni < 3; ++ni)
            wmma::store_matrix_sync(dst + (size_t)(rowOff + mi*16)*G3
                                        + nBase + colOff + ni*16,
                                    acc[mi][ni], G3, wmma::mem_row_major);
}

// ---------------- prep kernels ----------------
__global__ void k_idx(const float* __restrict__ gt, const float* __restrict__ gotoken){
    int w = (blockIdx.x*blockDim.x + threadIdx.x) >> 5;
    int lane = threadIdx.x & 31;
    if (w >= RWS) return;
    int s = w / Bb, b = w % Bb;
    const float* src = (s == 0) ? gotoken : gt + ((size_t)b*Ss + (s-1))*Oo;
    int found = Oo - 1;
    for (int o = lane; o < Oo; o += 32)
        if (src[o] > 0.5f) found = o;
    #pragma unroll
    for (int off = 16; off; off >>= 1)
        found = min(found, __shfl_xor_sync(0xffffffffu, found, off));
    if (lane == 0) g_idx[w] = found;
}

__global__ void k_yT(const float* __restrict__ y){
    size_t t = (size_t)blockIdx.x*blockDim.x + threadIdx.x;
    if (t >= (size_t)RWS*Ii) return;
    int i = (int)(t % Ii); int r = (int)(t / Ii);
    int s = r / Bb, b = r % Bb;
    g_yT[t] = y[((size_t)b*Ss + s)*Ii + i];
}

__global__ void k_h0(const float* __restrict__ hx){
    int t = blockIdx.x*blockDim.x + threadIdx.x;
    if (t < Bb*Hh){
        float v = hx[t];
        g_hs[t] = v;
        __nv_bfloat16 h = __float2bfloat16(v);
        g_hH16[t] = h;
        g_hL16[t] = __float2bfloat16(v - __bfloat162float(h));
    }
}

__global__ void k_convWhh(const float* __restrict__ W){
    int t = blockIdx.x*blockDim.x + threadIdx.x;
    float v = W[t];
    __nv_bfloat16 h = __float2bfloat16(v);
    g_WhhHi[t] = h;
    g_WhhLo[t] = __float2bfloat16(v - __bfloat162float(h));
}
__global__ void k_convWih(const float* __restrict__ W){
    int t = blockIdx.x*blockDim.x + threadIdx.x;
    float v = W[t];
    __nv_bfloat16 h = __float2bfloat16(v);
    g_WihHi[t] = h;
    g_WihLo[t] = __float2bfloat16(v - __bfloat162float(h));
}
__global__ void k_convLw(const float* __restrict__ W){
    int t = blockIdx.x*blockDim.x + threadIdx.x;
    float v = W[t];
    __nv_bfloat16 h = __float2bfloat16(v);
    g_LwHi[t] = h;
    g_LwLo[t] = __float2bfloat16(v - __bfloat162float(h));
}

__global__ void k_prepT(const float* __restrict__ Wih){
    __shared__ float tile[32][33];
    int gB = blockIdx.x*32, oB = blockIdx.y*32;
    int tx = threadIdx.x, ty = threadIdx.y;
    #pragma unroll
    for (int j = 0; j < 32; j += 8)
        tile[ty+j][tx] = Wih[(size_t)(gB + ty + j)*1024 + 512 + oB + tx];
    __syncthreads();
    #pragma unroll
    for (int j = 0; j < 32; j += 8)
        g_WtgtT[(size_t)(oB + ty + j)*3072 + gB + tx] = tile[tx][ty+j];
}

// ---------------- GEMM kernels ----------------
__global__ void __launch_bounds__(256, 1) k_giW(){
    wmma_gemm(g_yT, 512, blockIdx.y*128,
              g_WihHi, g_WihLo, 1024, blockIdx.x*128, 0, 16,
              g_gi, 3072);
}

__global__ void __launch_bounds__(256, 1) k_lwW(){
    wmma_gemm(g_hsB, 1024, blockIdx.y*128,
              g_LwHi, g_LwLo, 1024, blockIdx.x*128, 0, 32,
              g_lg, 512);
}

// ---------------- gates: float4 vectorized + fused bih/one-hot gather ----------------
__global__ void k_gates(const float* __restrict__ bhh, const float* __restrict__ bih,
                        float* __restrict__ pre_out, int s){
    int t = blockIdx.x*blockDim.x + threadIdx.x;   // 32768 threads
    int b = t >> 8;
    int j = (t & 255) << 2;
    int row = s*Bb + b;
    int idx = g_idx[row];
    const float* wt = g_WtgtT + (size_t)idx*3072;
    size_t gio = (size_t)row*G3 + j;
    float4 ir  = *reinterpret_cast<const float4*>(g_gi + gio);
    float4 iz  = *reinterpret_cast<const float4*>(g_gi + gio + Hh);
    float4 inn = *reinterpret_cast<const float4*>(g_gi + gio + 2*Hh);
    float4 br4 = *reinterpret_cast<const float4*>(bih + j);
    float4 bz4 = *reinterpret_cast<const float4*>(bih + Hh + j);
    float4 bn4 = *reinterpret_cast<const float4*>(bih + 2*Hh + j);
    float4 wr4 = *reinterpret_cast<const float4*>(wt + j);
    float4 wz4 = *reinterpret_cast<const float4*>(wt + Hh + j);
    float4 wn4 = *reinterpret_cast<const float4*>(wt + 2*Hh + j);
    // (gemm + bih) + wtgt — same grouping as the old k_giBias epilogue
    ir.x = (ir.x + br4.x) + wr4.x; ir.y = (ir.y + br4.y) + wr4.y;
    ir.z = (ir.z + br4.z) + wr4.z; ir.w = (ir.w + br4.w) + wr4.w;
    iz.x = (iz.x + bz4.x) + wz4.x; iz.y = (iz.y + bz4.y) + wz4.y;
    iz.z = (iz.z + bz4.z) + wz4.z; iz.w = (iz.w + bz4.w) + wz4.w;
    inn.x = (inn.x + bn4.x) + wn4.x; inn.y = (inn.y + bn4.y) + wn4.y;
    inn.z = (inn.z + bn4.z) + wn4.z; inn.w = (inn.w + bn4.w) + wn4.w;

    size_t gho = (size_t)b*G3 + j;
    float4 hr = *reinterpret_cast<const float4*>(bhh + j);
    float4 hz = *reinterpret_cast<const float4*>(bhh + Hh + j);
    float4 hn = *reinterpret_cast<const float4*>(bhh + 2*Hh + j);
    #pragma unroll
    for (int kz = 0; kz < 4; ++kz){
        size_t o = (size_t)kz*Bb*G3 + gho;
        float4 r = *reinterpret_cast<const float4*>(g_gh4 + o);
        float4 z = *reinterpret_cast<const float4*>(g_gh4 + o + Hh);
        float4 n = *reinterpret_cast<const float4*>(g_gh4 + o + 2*Hh);
        hr.x += r.x; hr.y += r.y; hr.z += r.z; hr.w += r.w;
        hz.x += z.x; hz.y += z.y; hz.z += z.z; hz.w += z.w;
        hn.x += n.x; hn.y += n.y; hn.z += n.z; hn.w += n.w;
    }
    float4 hp = *reinterpret_cast<const float4*>(g_hs + ((size_t)s*Bb + b)*Hh + j);
    float pr[4], hy[4];
    float irv[4] = {ir.x, ir.y, ir.z, ir.w};
    float izv[4] = {iz.x, iz.y, iz.z, iz.w};
    float inv_[4] = {inn.x, inn.y, inn.z, inn.w};
    float hrv[4] = {hr.x, hr.y, hr.z, hr.w};
    float hzv[4] = {hz.x, hz.y, hz.z, hz.w};
    float hnv[4] = {hn.x, hn.y, hn.z, hn.w};
    float hpv[4] = {hp.x, hp.y, hp.z, hp.w};
    #pragma unroll
    for (int i = 0; i < 4; ++i){
        float rg = 1.f/(1.f + expf(-(irv[i] + hrv[i])));
        float zg = 1.f/(1.f + expf(-(izv[i] + hzv[i])));
        float pre = inv_[i] + rg*hnv[i];
        float ng = tanhf(pre);
        pr[i] = pre;
        hy[i] = ng + zg*(hpv[i] - ng);
    }
    float4 hyv = make_float4(hy[0], hy[1], hy[2], hy[3]);
    float4 prv = make_float4(pr[0], pr[1], pr[2], pr[3]);
    *reinterpret_cast<float4*>(g_hs + ((size_t)(s+1)*Bb + b)*Hh + j) = hyv;
    size_t ob = ((size_t)b*Ss + s)*Hh + j;
    *reinterpret_cast<float4*>(g_hsB + ob) = hyv;
    *reinterpret_cast<float4*>(pre_out + ob) = prv;
    uint32_t hh[4], hl[4];
    #pragma unroll
    for (int i = 0; i < 4; ++i){
        __nv_bfloat16 h = __float2bfloat16(hy[i]);
        hh[i] = __bfloat16_as_ushort(h);
        hl[i] = __bfloat16_as_ushort(__float2bfloat16(hy[i] - __bfloat162float(h)));
    }
    uint2 wH = make_uint2((hh[1]<<16)|hh[0], (hh[3]<<16)|hh[2]);
    uint2 wL = make_uint2((hl[1]<<16)|hl[0], (hl[3]<<16)|hl[2]);
    *reinterpret_cast<uint2*>(g_hH16 + (size_t)b*Hh + j) = wH;
    *reinterpret_cast<uint2*>(g_hL16 + (size_t)b*Hh + j) = wL;
}

// ---------------- softmax + argmax ----------------
__global__ void k_softmax(const float* __restrict__ lb,
                          float* __restrict__ probs, float* __restrict__ samp){
    __shared__ float sv[128];
    __shared__ int   si[128];
    int row = blockIdx.x;
    int t = threadIdx.x;
    const float* lgi = g_lg + (size_t)row*Oo;
    float v[4];
    #pragma unroll
    for (int i = 0; i < 4; ++i) v[i] = lgi[t + i*128] + lb[t + i*128];
    float lmax = v[0]; int lidx = t;
    #pragma unroll
    for (int i = 1; i < 4; ++i)
        if (v[i] > lmax){ lmax = v[i]; lidx = t + i*128; }
    sv[t] = lmax; si[t] = lidx; __syncthreads();
    for (int off = 64; off; off >>= 1){
        if (t < off){
            float v2 = sv[t+off]; int i2 = si[t+off];
            if (v2 > sv[t] || (v2 == sv[t] && i2 < si[t])){ sv[t] = v2; si[t] = i2; }
        }
        __syncthreads();
    }
    float rmax = sv[0]; int ridx = si[0];
    __syncthreads();
    float e[4]; float ls = 0.f;
    #pragma unroll
    for (int i = 0; i < 4; ++i){ e[i] = expf(v[i] - rmax); ls += e[i]; }
    sv[t] = ls; __syncthreads();
    for (int off = 64; off; off >>= 1){
        if (t < off) sv[t] += sv[t+off];
        __syncthreads();
    }
    float inv = 1.f/sv[0];
    float* lg = probs + (size_t)row*Oo;
    float* sp = samp + (size_t)row*Oo;
    #pragma unroll
    for (int i = 0; i < 4; ++i){
        int p = t + i*128;
        lg[p] = e[i]*inv;
        sp[p] = (p == ridx) ? 1.f : 0.f;
    }
}

__global__ void k_hxout(float* __restrict__ out){
    int t = blockIdx.x*blockDim.x + threadIdx.x;
    if (t < Bb*Hh) out[t] = g_hs[(size_t)Ss*Bb*Hh + t];
}

// ---------------- launch ----------------
extern "C" void kernel_launch(void* const* d_in, const int* in_sizes, int n_in,
                              void* d_out, int out_size){
    const float* y    = (const float*)d_in[0];
    const float* gt   = (const float*)d_in[1];
    const float* hx   = (const float*)d_in[2];
    const float* Wih  = (const float*)d_in[3];
    const float* bih  = (const float*)d_in[4];
    const float* Whh  = (const float*)d_in[5];
    const float* bhh  = (const float*)d_in[6];
    const float* lw   = (const float*)d_in[7];
    const float* lb   = (const float*)d_in[8];
    const float* gotk = (const float*)d_in[9];
    float* out = (float*)d_out;

    float* out_probs = out;
    float* out_pre   = out + (size_t)16777216;
    float* out_samp  = out + (size_t)50331648;
    float* out_hx    = out + (size_t)67108864;

    static int attr_set = 0;
    if (!attr_set){
        cudaFuncSetAttribute(k_ghB, cudaFuncAttributeMaxDynamicSharedMemorySize, 2*STG96*4);
        attr_set = 1;
    }

    k_idx    <<<RWS/8, 256>>>(gt, gotk);
    k_yT     <<<65536, 256>>>(y);
    k_h0     <<<Bb*Hh/256, 256>>>(hx);
    k_convWhh<<<12288, 256>>>(Whh);
    k_convWih<<<12288, 256>>>(Wih);
    k_convLw <<<2048, 256>>>(lw);
    k_prepT  <<<dim3(96, 16), dim3(32, 8)>>>(Wih);

    k_giW    <<<dim3(24, 256), 256>>>();

    for (int s = 0; s < Ss; ++s){
        k_ghB  <<<dim3(32, 4), 256, 2*STG96*4>>>();
        k_gates<<<128, 256>>>(bhh, bih, out_pre, s);
    }

    k_lwW    <<<dim3(4, 256), 256>>>();
    k_softmax<<<RWS, 128>>>(lb, out_probs, out_samp);
    k_hxout  <<<Bb*Hh/256, 256>>>(out_hx);
}

// round 16
// speedup vs baseline: 1.0360x; 1.0360x over previous
#include <cuda_runtime.h>
#include <cuda_bf16.h>
#include <mma.h>
#include <math.h>
#include <cstdint>

using namespace nvcuda;

#define Bb 128
#define Ss 256
#define Ii 512
#define Oo 512
#define Hh 1024
#define G3 3072
#define RWS (Ss*Bb)

// ---------------- scratch ----------------
__device__ __align__(16) float g_yT[16777216];    // [s*B+b][I]
__device__ int   g_idx[RWS];
__device__ __align__(16) float g_gi[100663296];   // [s*B+b][3H]
__device__ __align__(16) float g_gh4[4*Bb*G3];    // 4 K-split partials
__device__ __align__(16) float g_hs[33685504];    // [(s+1)][B][H]
__device__ __align__(16) float g_hsB[33554432];   // [b*S+s][H]
__device__ __align__(16) float g_lg[16777216];    // raw logits
__device__ __align__(16) float g_WtgtT[Oo*G3];
__device__ __align__(16) __nv_bfloat16 g_hH16[Bb*Hh], g_hL16[Bb*Hh];
__device__ __align__(16) __nv_bfloat16 g_WhhHi[G3*1024], g_WhhLo[G3*1024];
__device__ __align__(16) __nv_bfloat16 g_WihHi[G3*1024], g_WihLo[G3*1024];
__device__ __align__(16) __nv_bfloat16 g_LwHi[Oo*1024],  g_LwLo[Oo*1024];

typedef wmma::fragment<wmma::matrix_a, 16,16,16, __nv_bfloat16, wmma::row_major> FragA;
typedef wmma::fragment<wmma::matrix_b, 16,16,16, __nv_bfloat16, wmma::col_major> FragB;
typedef wmma::fragment<wmma::accumulator, 16,16,16, float> FragC;

#define SROW 20
#define SROW_E 40
#define STG96  8960

__device__ __forceinline__ void cvt16(const float4 v0, const float4 v1, uint4& hi, uint4& lo){
    __nv_bfloat16 h0, h1, l0, l1;
    h0=__float2bfloat16(v0.x); h1=__float2bfloat16(v0.y);
    l0=__float2bfloat16(v0.x-__bfloat162float(h0)); l1=__float2bfloat16(v0.y-__bfloat162float(h1));
    hi.x = ((uint32_t)__bfloat16_as_ushort(h1)<<16) | __bfloat16_as_ushort(h0);
    lo.x = ((uint32_t)__bfloat16_as_ushort(l1)<<16) | __bfloat16_as_ushort(l0);
    h0=__float2bfloat16(v0.z); h1=__float2bfloat16(v0.w);
    l0=__float2bfloat16(v0.z-__bfloat162float(h0)); l1=__float2bfloat16(v0.w-__bfloat162float(h1));
    hi.y = ((uint32_t)__bfloat16_as_ushort(h1)<<16) | __bfloat16_as_ushort(h0);
    lo.y = ((uint32_t)__bfloat16_as_ushort(l1)<<16) | __bfloat16_as_ushort(l0);
    h0=__float2bfloat16(v1.x); h1=__float2bfloat16(v1.y);
    l0=__float2bfloat16(v1.x-__bfloat162float(h0)); l1=__float2bfloat16(v1.y-__bfloat162float(h1));
    hi.z = ((uint32_t)__bfloat16_as_ushort(h1)<<16) | __bfloat16_as_ushort(h0);
    lo.z = ((uint32_t)__bfloat16_as_ushort(l1)<<16) | __bfloat16_as_ushort(l0);
    h0=__float2bfloat16(v1.z); h1=__float2bfloat16(v1.w);
    l0=__float2bfloat16(v1.z-__bfloat162float(h0)); l1=__float2bfloat16(v1.w-__bfloat162float(h1));
    hi.w = ((uint32_t)__bfloat16_as_ushort(h1)<<16) | __bfloat16_as_ushort(h0);
    lo.w = ((uint32_t)__bfloat16_as_ushort(l1)<<16) | __bfloat16_as_ushort(l0);
}

// ---------------- wmma compute stages ----------------
__device__ __forceinline__ void mma_stage(
    const uint32_t* sAHi, const uint32_t* sALo,
    const uint32_t* sBHi, const uint32_t* sBLo,
    int rowOff, int colOff, FragC acc[2][4])
{
    const __nv_bfloat16* eAh = reinterpret_cast<const __nv_bfloat16*>(sAHi);
    const __nv_bfloat16* eAl = reinterpret_cast<const __nv_bfloat16*>(sALo);
    const __nv_bfloat16* eBh = reinterpret_cast<const __nv_bfloat16*>(sBHi);
    const __nv_bfloat16* eBl = reinterpret_cast<const __nv_bfloat16*>(sBLo);
    #pragma unroll
    for (int ks = 0; ks < 2; ++ks){
        FragA ah[2], al[2];
        #pragma unroll
        for (int mi = 0; mi < 2; ++mi){
            wmma::load_matrix_sync(ah[mi], eAh + (rowOff + mi*16)*SROW_E + ks*16, SROW_E);
            wmma::load_matrix_sync(al[mi], eAl + (rowOff + mi*16)*SROW_E + ks*16, SROW_E);
        }
        #pragma unroll
        for (int ni = 0; ni < 4; ++ni){
            FragB bh, bl;
            wmma::load_matrix_sync(bh, eBh + (colOff + ni*16)*SROW_E + ks*16, SROW_E);
            wmma::load_matrix_sync(bl, eBl + (colOff + ni*16)*SROW_E + ks*16, SROW_E);
            #pragma unroll
            for (int mi = 0; mi < 2; ++mi){
                wmma::mma_sync(acc[mi][ni], ah[mi], bh, acc[mi][ni]);
                wmma::mma_sync(acc[mi][ni], ah[mi], bl, acc[mi][ni]);
                wmma::mma_sync(acc[mi][ni], al[mi], bh, acc[mi][ni]);
            }
        }
    }
}

__device__ __forceinline__ void mma_stage96(
    const uint32_t* sAHi, const uint32_t* sALo,
    const uint32_t* sBHi, const uint32_t* sBLo,
    int rowOff, int colOff, FragC acc[2][3])
{
    const __nv_bfloat16* eAh = reinterpret_cast<const __nv_bfloat16*>(sAHi);
    const __nv_bfloat16* eAl = reinterpret_cast<const __nv_bfloat16*>(sALo);
    const __nv_bfloat16* eBh = reinterpret_cast<const __nv_bfloat16*>(sBHi);
    const __nv_bfloat16* eBl = reinterpret_cast<const __nv_bfloat16*>(sBLo);
    #pragma unroll
    for (int ks = 0; ks < 2; ++ks){
        FragA ah[2], al[2];
        #pragma unroll
        for (int mi = 0; mi < 2; ++mi){
            wmma::load_matrix_sync(ah[mi], eAh + (rowOff + mi*16)*SROW_E + ks*16, SROW_E);
            wmma::load_matrix_sync(al[mi], eAl + (rowOff + mi*16)*SROW_E + ks*16, SROW_E);
        }
        #pragma unroll
        for (int ni = 0; ni < 3; ++ni){
            FragB bh, bl;
            wmma::load_matrix_sync(bh, eBh + (colOff + ni*16)*SROW_E + ks*16, SROW_E);
            wmma::load_matrix_sync(bl, eBl + (colOff + ni*16)*SROW_E + ks*16, SROW_E);
            #pragma unroll
            for (int mi = 0; mi < 2; ++mi){
                wmma::mma_sync(acc[mi][ni], ah[mi], bh, acc[mi][ni]);
                wmma::mma_sync(acc[mi][ni], ah[mi], bl, acc[mi][ni]);
                wmma::mma_sync(acc[mi][ni], al[mi], bh, acc[mi][ni]);
            }
        }
    }
}

__device__ __forceinline__ void copy_tile16(uint32_t* dst, const __nv_bfloat16* __restrict__ src,
                                            int ld, int rowBase, int k0){
    int t = threadIdx.x;
    #pragma unroll
    for (int it = 0; it < 2; ++it){
        int idx = it*256 + t;
        int row = idx >> 2, seg = idx & 3;
        *reinterpret_cast<uint4*>(dst + row*SROW + seg*4) =
            *reinterpret_cast<const uint4*>(src + (size_t)(rowBase+row)*ld + k0 + seg*8);
    }
}

// ---------------- wmma GEMM, static smem (R13-proven; 2 CTA/SM) ----------------
__device__ __forceinline__ void wmma_gemm(
    const float* __restrict__ Asrc, int lda, int mBase,
    const __nv_bfloat16* __restrict__ BHi, const __nv_bfloat16* __restrict__ BLo,
    int ldb, int nBase, int k0, int nChunks,
    float* __restrict__ dst, int ldd)
{
    __shared__ __align__(16) uint32_t sAHi[128*SROW], sALo[128*SROW];
    __shared__ __align__(16) uint32_t sBHi[128*SROW], sBLo[128*SROW];
    int t = threadIdx.x;
    FragC acc[2][4];
    #pragma unroll
    for (int mi = 0; mi < 2; ++mi)
        #pragma unroll
        for (int ni = 0; ni < 4; ++ni) wmma::fill_fragment(acc[mi][ni], 0.f);
    int w = t >> 5;
    int rowOff = (w&3)*32, colOff = (w>>2)*64;
    for (int c = 0; c < nChunks; ++c){
        int kc = k0 + c*32;
        #pragma unroll
        for (int it = 0; it < 2; ++it){
            int idx = it*256 + t;
            int row = idx >> 2, seg = idx & 3;
            const float* p = Asrc + (size_t)(mBase + row)*lda + kc + seg*8;
            float4 v0 = *reinterpret_cast<const float4*>(p);
            float4 v1 = *reinterpret_cast<const float4*>(p + 4);
            uint4 hi, lo; cvt16(v0, v1, hi, lo);
            *reinterpret_cast<uint4*>(sAHi + row*SROW + seg*4) = hi;
            *reinterpret_cast<uint4*>(sALo + row*SROW + seg*4) = lo;
        }
        copy_tile16(sBHi, BHi, ldb, nBase, kc);
        copy_tile16(sBLo, BLo, ldb, nBase, kc);
        __syncthreads();
        mma_stage(sAHi, sALo, sBHi, sBLo, rowOff, colOff, acc);
        __syncthreads();
    }
    #pragma unroll
    for (int mi = 0; mi < 2; ++mi)
        #pragma unroll
        for (int ni = 0; ni < 4; ++ni)
            wmma::store_matrix_sync(dst + (size_t)(mBase + rowOff + mi*16)*ldd
                                        + nBase + colOff + ni*16,
                                    acc[mi][ni], ldd, wmma::mem_row_major);
}

// ---------------- recurrence GEMM (R13 verbatim) ----------------
__global__ void __launch_bounds__(256, 1) k_ghB(){
    extern __shared__ __align__(16) uint32_t smb[];
    int nt = blockIdx.x, kz = blockIdx.y;
    int nBase = nt*96, k0 = kz*256;
    int t = threadIdx.x, w = t >> 5;
    int rowOff = (w&3)*32, colOff = (w>>2)*48;
    int ra0 = t >> 2,          sa0 = t & 3;
    int ra1 = (256+t) >> 2,    sa1 = t & 3;
    size_t a0 = (size_t)ra0*1024 + sa0*8,  a1 = (size_t)ra1*1024 + sa1*8;
    int da0 = ra0*SROW + sa0*4, da1 = ra1*SROW + sa1*4;
    int rb0 = t >> 2,          sb0 = t & 3;
    int rb1 = 64 + (t >> 2),   sb1 = t & 3;
    bool hasB1 = (t < 128);
    size_t b0 = (size_t)(nBase+rb0)*1024 + sb0*8;
    size_t b1 = (size_t)(nBase+rb1)*1024 + sb1*8;
    int db0 = rb0*SROW + sb0*4, db1 = rb1*SROW + sb1*4;

    FragC acc[2][3];
    #pragma unroll
    for (int mi = 0; mi < 2; ++mi)
        #pragma unroll
        for (int ni = 0; ni < 3; ++ni) wmma::fill_fragment(acc[mi][ni], 0.f);

    {
        int kc = k0;
        uint32_t* st = smb;
        *reinterpret_cast<uint4*>(st + da0)        = *reinterpret_cast<const uint4*>(g_hH16 + a0 + kc);
        *reinterpret_cast<uint4*>(st + da1)        = *reinterpret_cast<const uint4*>(g_hH16 + a1 + kc);
        *reinterpret_cast<uint4*>(st + 2560 + da0) = *reinterpret_cast<const uint4*>(g_hL16 + a0 + kc);
        *reinterpret_cast<uint4*>(st + 2560 + da1) = *reinterpret_cast<const uint4*>(g_hL16 + a1 + kc);
        *reinterpret_cast<uint4*>(st + 5120 + db0) = *reinterpret_cast<const uint4*>(g_WhhHi + b0 + kc);
        *reinterpret_cast<uint4*>(st + 7040 + db0) = *reinterpret_cast<const uint4*>(g_WhhLo + b0 + kc);
        if (hasB1){
            *reinterpret_cast<uint4*>(st + 5120 + db1) = *reinterpret_cast<const uint4*>(g_WhhHi + b1 + kc);
            *reinterpret_cast<uint4*>(st + 7040 + db1) = *reinterpret_cast<const uint4*>(g_WhhLo + b1 + kc);
        }
    }
    __syncthreads();

    #pragma unroll
    for (int c = 0; c < 8; ++c){
        uint4 rAh0, rAh1, rAl0, rAl1, rBh0, rBh1, rBl0, rBl1;
        if (c < 7){
            int kc = k0 + (c+1)*32;
            rAh0 = *reinterpret_cast<const uint4*>(g_hH16 + a0 + kc);
            rAh1 = *reinterpret_cast<const uint4*>(g_hH16 + a1 + kc);
            rAl0 = *reinterpret_cast<const uint4*>(g_hL16 + a0 + kc);
            rAl1 = *reinterpret_cast<const uint4*>(g_hL16 + a1 + kc);
            rBh0 = *reinterpret_cast<const uint4*>(g_WhhHi + b0 + kc);
            rBl0 = *reinterpret_cast<const uint4*>(g_WhhLo + b0 + kc);
            if (hasB1){
                rBh1 = *reinterpret_cast<const uint4*>(g_WhhHi + b1 + kc);
                rBl1 = *reinterpret_cast<const uint4*>(g_WhhLo + b1 + kc);
            }
        }
        const uint32_t* st = smb + (c & 1)*STG96;
        mma_stage96(st, st + 2560, st + 5120, st + 7040, rowOff, colOff, acc);
        if (c < 7){
            uint32_t* dt = smb + ((c+1) & 1)*STG96;
            *reinterpret_cast<uint4*>(dt + da0)        = rAh0;
            *reinterpret_cast<uint4*>(dt + da1)        = rAh1;
            *reinterpret_cast<uint4*>(dt + 2560 + da0) = rAl0;
            *reinterpret_cast<uint4*>(dt + 2560 + da1) = rAl1;
            *reinterpret_cast<uint4*>(dt + 5120 + db0) = rBh0;
            *reinterpret_cast<uint4*>(dt + 7040 + db0) = rBl0;
            if (hasB1){
                *reinterpret_cast<uint4*>(dt + 5120 + db1) = rBh1;
                *reinterpret_cast<uint4*>(dt + 7040 + db1) = rBl1;
            }
        }
        __syncthreads();
    }
    float* dst = g_gh4 + (size_t)kz*Bb*G3;
    #pragma unroll
    for (int mi = 0; mi < 2; ++mi)
        #pragma unroll
        for (int ni = 0; ni < 3; ++ni)
            wmma::store_matrix_sync(dst + (size_t)(rowOff + mi*16)*G3
                                        + nBase + colOff + ni*16,
                                    acc[mi][ni], G3, wmma::mem_row_major);
}

// ---------------- prep kernels ----------------
__global__ void k_idx(const float* __restrict__ gt, const float* __restrict__ gotoken){
    int w = (blockIdx.x*blockDim.x + threadIdx.x) >> 5;
    int lane = threadIdx.x & 31;
    if (w >= RWS) return;
    int s = w / Bb, b = w % Bb;
    const float* src = (s == 0) ? gotoken : gt + ((size_t)b*Ss + (s-1))*Oo;
    int found = Oo - 1;
    for (int o = lane; o < Oo; o += 32)
        if (src[o] > 0.5f) found = o;
    #pragma unroll
    for (int off = 16; off; off >>= 1)
        found = min(found, __shfl_xor_sync(0xffffffffu, found, off));
    if (lane == 0) g_idx[w] = found;
}

__global__ void k_yT(const float* __restrict__ y){
    size_t t = (size_t)blockIdx.x*blockDim.x + threadIdx.x;
    if (t >= (size_t)RWS*Ii) return;
    int i = (int)(t % Ii); int r = (int)(t / Ii);
    int s = r / Bb, b = r % Bb;
    g_yT[t] = y[((size_t)b*Ss + s)*Ii + i];
}

__global__ void k_h0(const float* __restrict__ hx){
    int t = blockIdx.x*blockDim.x + threadIdx.x;
    if (t < Bb*Hh){
        float v = hx[t];
        g_hs[t] = v;
        __nv_bfloat16 h = __float2bfloat16(v);
        g_hH16[t] = h;
        g_hL16[t] = __float2bfloat16(v - __bfloat162float(h));
    }
}

__global__ void k_convWhh(const float* __restrict__ W){
    int t = blockIdx.x*blockDim.x + threadIdx.x;
    float v = W[t];
    __nv_bfloat16 h = __float2bfloat16(v);
    g_WhhHi[t] = h;
    g_WhhLo[t] = __float2bfloat16(v - __bfloat162float(h));
}
__global__ void k_convWih(const float* __restrict__ W){
    int t = blockIdx.x*blockDim.x + threadIdx.x;
    float v = W[t];
    __nv_bfloat16 h = __float2bfloat16(v);
    g_WihHi[t] = h;
    g_WihLo[t] = __float2bfloat16(v - __bfloat162float(h));
}
__global__ void k_convLw(const float* __restrict__ W){
    int t = blockIdx.x*blockDim.x + threadIdx.x;
    float v = W[t];
    __nv_bfloat16 h = __float2bfloat16(v);
    g_LwHi[t] = h;
    g_LwLo[t] = __float2bfloat16(v - __bfloat162float(h));
}

__global__ void k_prepT(const float* __restrict__ Wih){
    __shared__ float tile[32][33];
    int gB = blockIdx.x*32, oB = blockIdx.y*32;
    int tx = threadIdx.x, ty = threadIdx.y;
    #pragma unroll
    for (int j = 0; j < 32; j += 8)
        tile[ty+j][tx] = Wih[(size_t)(gB + ty + j)*1024 + 512 + oB + tx];
    __syncthreads();
    #pragma unroll
    for (int j = 0; j < 32; j += 8)
        g_WtgtT[(size_t)(oB + ty + j)*3072 + gB + tx] = tile[tx][ty+j];
}

// ---------------- GEMM kernels ----------------
__global__ void __launch_bounds__(256, 1) k_giW(int mBase){
    wmma_gemm(g_yT, 512, mBase + blockIdx.y*128,
              g_WihHi, g_WihLo, 1024, blockIdx.x*128, 0, 16,
              g_gi, 3072);
}

__global__ void __launch_bounds__(256, 1) k_lwW(){
    wmma_gemm(g_hsB, 1024, blockIdx.y*128,
              g_LwHi, g_LwLo, 1024, blockIdx.x*128, 0, 32,
              g_lg, 512);
}

// gi epilogue chunk: rows [rowBase, rowBase+4096)
__global__ void k_giBias(const float* __restrict__ bih, int rowBase){
    int idx = blockIdx.x*blockDim.x + threadIdx.x;   // 3145728 float4 tasks
    int row = rowBase + idx / 768;
    int n4 = (idx % 768)*4;
    int id = g_idx[row];
    float4 v = *reinterpret_cast<float4*>(g_gi + (size_t)row*3072 + n4);
    float4 b = *reinterpret_cast<const float4*>(bih + n4);
    float4 wv = *reinterpret_cast<const float4*>(g_WtgtT + (size_t)id*3072 + n4);
    v.x += b.x + wv.x; v.y += b.y + wv.y; v.z += b.z + wv.z; v.w += b.w + wv.w;
    *reinterpret_cast<float4*>(g_gi + (size_t)row*3072 + n4) = v;
}

// ---------------- gates (R13 verbatim) ----------------
__global__ void k_gates(const float* __restrict__ bhh, float* __restrict__ pre_out, int s){
    int t = blockIdx.x*blockDim.x + threadIdx.x;
    if (t >= Bb*Hh) return;
    int b = t >> 10, j = t & 1023;
    size_t gio = ((size_t)s*Bb + b)*G3 + j;
    float i_r = g_gi[gio], i_z = g_gi[gio + Hh], i_n = g_gi[gio + 2*Hh];
    size_t gho = (size_t)b*G3 + j;
    float h_r = bhh[j], h_z = bhh[Hh + j], h_n = bhh[2*Hh + j];
    #pragma unroll
    for (int kz = 0; kz < 4; ++kz){
        size_t o = (size_t)kz*Bb*G3 + gho;
        h_r += g_gh4[o]; h_z += g_gh4[o + Hh]; h_n += g_gh4[o + 2*Hh];
    }
    float rg = 1.f/(1.f + expf(-(i_r + h_r)));
    float zg = 1.f/(1.f + expf(-(i_z + h_z)));
    float pre = i_n + rg*h_n;
    float ng = tanhf(pre);
    float hp = g_hs[((size_t)s*Bb + b)*Hh + j];
    float hy = ng + zg*(hp - ng);
    g_hs [((size_t)(s+1)*Bb + b)*Hh + j] = hy;
    g_hsB[((size_t)b*Ss + s)*Hh + j]     = hy;
    pre_out[((size_t)b*Ss + s)*Hh + j]   = pre;
    __nv_bfloat16 hh = __float2bfloat16(hy);
    g_hH16[t] = hh;
    g_hL16[t] = __float2bfloat16(hy - __bfloat162float(hh));
}

// ---------------- softmax + argmax ----------------
__global__ void k_softmax(const float* __restrict__ lb,
                          float* __restrict__ probs, float* __restrict__ samp){
    __shared__ float sv[128];
    __shared__ int   si[128];
    int row = blockIdx.x;
    int t = threadIdx.x;
    const float* lgi = g_lg + (size_t)row*Oo;
    float v[4];
    #pragma unroll
    for (int i = 0; i < 4; ++i) v[i] = lgi[t + i*128] + lb[t + i*128];
    float lmax = v[0]; int lidx = t;
    #pragma unroll
    for (int i = 1; i < 4; ++i)
        if (v[i] > lmax){ lmax = v[i]; lidx = t + i*128; }
    sv[t] = lmax; si[t] = lidx; __syncthreads();
    for (int off = 64; off; off >>= 1){
        if (t < off){
            float v2 = sv[t+off]; int i2 = si[t+off];
            if (v2 > sv[t] || (v2 == sv[t] && i2 < si[t])){ sv[t] = v2; si[t] = i2; }
        }
        __syncthreads();
    }
    float rmax = sv[0]; int ridx = si[0];
    __syncthreads();
    float e[4]; float ls = 0.f;
    #pragma unroll
    for (int i = 0; i < 4; ++i){ e[i] = expf(v[i] - rmax); ls += e[i]; }
    sv[t] = ls; __syncthreads();
    for (int off = 64; off; off >>= 1){
        if (t < off) sv[t] += sv[t+off];
        __syncthreads();
    }
    float inv = 1.f/sv[0];
    float* lg = probs + (size_t)row*Oo;
    float* sp = samp + (size_t)row*Oo;
    #pragma unroll
    for (int i = 0; i < 4; ++i){
        int p = t + i*128;
        lg[p] = e[i]*inv;
        sp[p] = (p == ridx) ? 1.f : 0.f;
    }
}

__global__ void k_hxout(float* __restrict__ out){
    int t = blockIdx.x*blockDim.x + threadIdx.x;
    if (t < Bb*Hh) out[t] = g_hs[(size_t)Ss*Bb*Hh + t];
}

// ---------------- launch ----------------
extern "C" void kernel_launch(void* const* d_in, const int* in_sizes, int n_in,
                              void* d_out, int out_size){
    const float* y    = (const float*)d_in[0];
    const float* gt   = (const float*)d_in[1];
    const float* hx   = (const float*)d_in[2];
    const float* Wih  = (const float*)d_in[3];
    const float* bih  = (const float*)d_in[4];
    const float* Whh  = (const float*)d_in[5];
    const float* bhh  = (const float*)d_in[6];
    const float* lw   = (const float*)d_in[7];
    const float* lb   = (const float*)d_in[8];
    const float* gotk = (const float*)d_in[9];
    float* out = (float*)d_out;

    float* out_probs = out;
    float* out_pre   = out + (size_t)16777216;
    float* out_samp  = out + (size_t)50331648;
    float* out_hx    = out + (size_t)67108864;

    static int init_done = 0;
    static cudaStream_t s2;
    static cudaEvent_t eFork, eGi[8];
    if (!init_done){
        cudaFuncSetAttribute(k_ghB, cudaFuncAttributeMaxDynamicSharedMemorySize, 2*STG96*4);
        cudaStreamCreateWithFlags(&s2, cudaStreamNonBlocking);
        cudaEventCreateWithFlags(&eFork, cudaEventDisableTiming);
        for (int i = 0; i < 8; ++i)
            cudaEventCreateWithFlags(&eGi[i], cudaEventDisableTiming);
        init_done = 1;
    }

    k_idx    <<<RWS/8, 256>>>(gt, gotk);
    k_yT     <<<65536, 256>>>(y);
    k_h0     <<<Bb*Hh/256, 256>>>(hx);
    k_convWhh<<<12288, 256>>>(Whh);
    k_convWih<<<12288, 256>>>(Wih);
    k_convLw <<<2048, 256>>>(lw);
    k_prepT  <<<dim3(96, 16), dim3(32, 8)>>>(Wih);

    // fork gi (GEMM + bias) onto s2, chunked by 32 steps
    cudaEventRecord(eFork, 0);
    cudaStreamWaitEvent(s2, eFork, 0);
    for (int ch = 0; ch < 8; ++ch){
        k_giW   <<<dim3(24, 32), 256, 0, s2>>>(ch*4096);
        k_giBias<<<12288, 256, 0, s2>>>(bih, ch*4096);
        cudaEventRecord(eGi[ch], s2);
    }

    for (int s = 0; s < Ss; ++s){
        if ((s & 31) == 0) cudaStreamWaitEvent(0, eGi[s >> 5], 0);
        k_ghB  <<<dim3(32, 4), 256, 2*STG96*4>>>();
        k_gates<<<Bb*Hh/256, 256>>>(bhh, out_pre, s);
    }

    k_lwW    <<<dim3(4, 256), 256>>>();
    k_softmax<<<RWS, 128>>>(lb, out_probs, out_samp);
    k_hxout  <<<Bb*Hh/256, 256>>>(out_hx);
}